// round 10
// baseline (speedup 1.0000x reference)
#include <cuda_runtime.h>
#include <cuda_fp16.h>
#include <math_constants.h>
#include <mma.h>

using namespace nvcuda;

#define NN    100000
#define EDGES 1600000
#define EE    (EDGES + NN)
#define F     128

// ---------------- device scratch (no allocation allowed) ----------------
__device__ uint2 g_hf[NN * 32];  // h = X@W in fp16 (128 halves = 32 uint2/node)
__device__ float g_f0[NN * F];
__device__ float g_f1[NN * F];
__device__ float g_as[NN * 4];
__device__ float g_ad[NN * 4];
__device__ int   g_deg[NN];
__device__ int   g_rs[NN + 1];
__device__ int   g_cnt[NN];
__device__ int   g_src[EE];

// ---------------- CSR build (by destination) ----------------
__global__ void csr_hist(const int* __restrict__ ei, int* __restrict__ deg)
{
    int e = blockIdx.x * blockDim.x + threadIdx.x;
    if (e >= EE) return;
    int d = (e < EDGES) ? ei[EDGES + e] : (e - EDGES);
    atomicAdd(&deg[d], 1);
}

__global__ __launch_bounds__(1024) void csr_scan(const int* __restrict__ deg,
                                                 int* __restrict__ rs)
{
    __shared__ int wsum[32];
    const int t    = threadIdx.x;
    const int lane = t & 31;
    const int w    = t >> 5;
    const int CH   = (NN + 1023) / 1024;
    const int lo   = t * CH;
    const int hi   = min(lo + CH, NN);

    int sum = 0;
    for (int i = lo; i < hi; i++) sum += deg[i];

    int inc = sum;
#pragma unroll
    for (int o = 1; o < 32; o <<= 1) {
        int x = __shfl_up_sync(0xffffffffu, inc, o);
        if (lane >= o) inc += x;
    }
    if (lane == 31) wsum[w] = inc;
    __syncthreads();
    if (w == 0) {
        int v = wsum[lane];
        int s = v;
#pragma unroll
        for (int o = 1; o < 32; o <<= 1) {
            int x = __shfl_up_sync(0xffffffffu, s, o);
            if (lane >= o) s += x;
        }
        wsum[lane] = s - v;
    }
    __syncthreads();

    int run = wsum[w] + inc - sum;
    for (int i = lo; i < hi; i++) { rs[i] = run; run += deg[i]; }
    if (t == 1023) rs[NN] = run;
}

__global__ void csr_fill(const int* __restrict__ ei,
                         const int* __restrict__ rs,
                         int* __restrict__ cnt, int* __restrict__ csrc)
{
    int e = blockIdx.x * blockDim.x + threadIdx.x;
    if (e >= EE) return;
    int s, d;
    if (e < EDGES) { s = ei[e]; d = ei[EDGES + e]; }
    else           { s = d = e - EDGES; }
    int pos = rs[d] + atomicAdd(&cnt[d], 1);
    csrc[pos] = s;
}

// ---------------- tf32 tensor-core GEMM + fused attention epilogue ----------
// BM=64, BN=128, 8 warps. Warp (wr, wc): rows wr*16..+15, cols wc*64..+63
// (4 wmma 16x16 tiles). K chunked x32, 4 k-steps of 8 per chunk.
// Accumulators staged to smem (aliased with input tiles) for the epilogue.
__global__ __launch_bounds__(256) void gemm_attn(
    const float* __restrict__ fin, const float* __restrict__ W,
    const float* __restrict__ att_s, const float* __restrict__ att_d,
    uint2* __restrict__ hf, float* __restrict__ as_, float* __restrict__ ad_,
    int H)
{
    __shared__ __align__(16) char sbuf[32768];     // max(Xs+Ws=24KB, Cs=32KB)
    float* Xs = (float*)sbuf;                       // [64][32]
    float* Ws = (float*)(sbuf + 64 * 32 * 4);       // [32][128]
    float* Cs = (float*)sbuf;                       // [64][128] (after mainloop)

    const int t    = threadIdx.x;
    const int warp = t >> 5;
    const int wr   = warp & 3;          // row group
    const int wc   = warp >> 2;         // col half
    const int row0 = blockIdx.x * 64;

    wmma::fragment<wmma::accumulator, 16, 16, 8, float> cfrag[4];
#pragma unroll
    for (int j = 0; j < 4; j++) wmma::fill_fragment(cfrag[j], 0.f);

    for (int kc = 0; kc < 4; kc++) {
        // X chunk 64x32 (2 float4/thread)
#pragma unroll
        for (int i = 0; i < 2; i++) {
            int idx = t + 256 * i;              // 0..511
            int r = idx >> 3, c = idx & 7;
            int gr = min(row0 + r, NN - 1);
            *(float4*)&Xs[r * 32 + 4 * c] =
                *(const float4*)&fin[gr * F + kc * 32 + 4 * c];
        }
        // W chunk 32x128 (4 float4/thread)
#pragma unroll
        for (int i = 0; i < 4; i++) {
            int idx = t + 256 * i;              // 0..1023
            int k = idx >> 5, c = idx & 31;
            *(float4*)&Ws[k * 128 + 4 * c] =
                *(const float4*)&W[(kc * 32 + k) * F + 4 * c];
        }
        __syncthreads();

#pragma unroll
        for (int ks = 0; ks < 4; ks++) {
            wmma::fragment<wmma::matrix_a, 16, 16, 8,
                           wmma::precision::tf32, wmma::row_major> af;
            wmma::load_matrix_sync(af, &Xs[wr * 16 * 32 + ks * 8], 32);
#pragma unroll
            for (int e = 0; e < af.num_elements; e++)
                af.x[e] = wmma::__float_to_tf32(af.x[e]);
#pragma unroll
            for (int j = 0; j < 4; j++) {
                wmma::fragment<wmma::matrix_b, 16, 16, 8,
                               wmma::precision::tf32, wmma::row_major> bf;
                wmma::load_matrix_sync(bf, &Ws[ks * 8 * 128 + wc * 64 + j * 16], 128);
#pragma unroll
                for (int e = 0; e < bf.num_elements; e++)
                    bf.x[e] = wmma::__float_to_tf32(bf.x[e]);
                wmma::mma_sync(cfrag[j], af, bf, cfrag[j]);
            }
        }
        __syncthreads();
    }

    // stage accumulators to smem
#pragma unroll
    for (int j = 0; j < 4; j++)
        wmma::store_matrix_sync(&Cs[wr * 16 * 128 + wc * 64 + j * 16],
                                cfrag[j], 128, wmma::mem_row_major);
    __syncthreads();

    // epilogue: thread t -> row t>>2, col quarter q = t&3 (cols q*32..+31).
    // For H=4, a 32-col quarter is exactly one head: no cross-head shuffles.
    const int r  = t >> 2;
    const int q  = t & 3;
    const int gr = row0 + r;
    const bool ok = gr < NN;

    float vals[32];
#pragma unroll
    for (int i = 0; i < 8; i++) {
        float4 v = *(float4*)&Cs[r * 128 + q * 32 + 4 * i];
        vals[4 * i + 0] = v.x; vals[4 * i + 1] = v.y;
        vals[4 * i + 2] = v.z; vals[4 * i + 3] = v.w;
    }

    if (ok) {
#pragma unroll
        for (int wq = 0; wq < 4; wq++) {        // 4 uint4 stores (8 halves each)
            __half2 a = __floats2half2_rn(vals[8 * wq + 0], vals[8 * wq + 1]);
            __half2 b2 = __floats2half2_rn(vals[8 * wq + 2], vals[8 * wq + 3]);
            __half2 c = __floats2half2_rn(vals[8 * wq + 4], vals[8 * wq + 5]);
            __half2 dd = __floats2half2_rn(vals[8 * wq + 6], vals[8 * wq + 7]);
            uint4 u;
            u.x = *(unsigned*)&a;  u.y = *(unsigned*)&b2;
            u.z = *(unsigned*)&c;  u.w = *(unsigned*)&dd;
            ((uint4*)hf)[gr * 16 + q * 4 + wq] = u;
        }
    }

    float ps = 0.f, pd = 0.f;
#pragma unroll
    for (int i = 0; i < 32; i++) {
        ps += vals[i] * att_s[q * 32 + i];
        pd += vals[i] * att_d[q * 32 + i];
    }
    if (H == 4) {
        if (ok) {
            as_[gr * 4 + q] = ps;
            ad_[gr * 4 + q] = pd;
        }
    } else {
        ps += __shfl_xor_sync(0xffffffffu, ps, 1);
        ps += __shfl_xor_sync(0xffffffffu, ps, 2);
        pd += __shfl_xor_sync(0xffffffffu, pd, 1);
        pd += __shfl_xor_sync(0xffffffffu, pd, 2);
        if (q == 0 && ok) { as_[gr] = ps; ad_[gr] = pd; }
    }
}

// ---------------- fused softmax + aggregate: warp per dst node ----------------
// (R7 version — best measured; fp16 h gather, fp32 accumulate)
__global__ __launch_bounds__(256) void gat_gather(
    const int* __restrict__ rs, const int* __restrict__ csrc,
    const float* __restrict__ as_, const float* __restrict__ ad_,
    const uint2* __restrict__ hf, const float* __restrict__ b,
    float* __restrict__ out, int H, int elu)
{
    const int warp = (blockIdx.x * blockDim.x + threadIdx.x) >> 5;
    const int lane = threadIdx.x & 31;
    if (warp >= NN) return;
    const int d = warp;

    const int h = (H == 4) ? (lane >> 3) : 0;
    const float adv = ad_[d * H + h];

    float m = -CUDART_INF_F, den = 0.f;
    float4 acc = make_float4(0.f, 0.f, 0.f, 0.f);

    const int start = rs[d], end = rs[d + 1];
    const int gbase = lane & 24;

    for (int j = start; j < end; j += 32) {
        int sj = (j + lane < end) ? csrc[j + lane] : 0;
        int nb = min(32, end - j);
        for (int base = 0; base < nb; base += 8) {
            int nk = min(8, nb - base);
            int  s_my  = __shfl_sync(0xffffffffu, sj, base + (lane & 7));
            bool valid = (lane & 7) < nk;
            float v = -CUDART_INF_F;
            if (valid) {
                float vv = as_[s_my * H + h] + adv;
                v = vv > 0.f ? vv : 0.2f * vv;
            }
            float bm = v;
            bm = fmaxf(bm, __shfl_xor_sync(0xffffffffu, bm, 1));
            bm = fmaxf(bm, __shfl_xor_sync(0xffffffffu, bm, 2));
            bm = fmaxf(bm, __shfl_xor_sync(0xffffffffu, bm, 4));
            float mn = fmaxf(m, bm);
            float f  = __expf(m - mn);
            float p  = valid ? __expf(v - mn) : 0.f;
            float ps = p;
            ps += __shfl_xor_sync(0xffffffffu, ps, 1);
            ps += __shfl_xor_sync(0xffffffffu, ps, 2);
            ps += __shfl_xor_sync(0xffffffffu, ps, 4);
            den = den * f + ps;
            m = mn;
            acc.x *= f; acc.y *= f; acc.z *= f; acc.w *= f;
            for (int k = 0; k < nk; k++) {
                int   s  = __shfl_sync(0xffffffffu, sj, base + k);
                float pk = __shfl_sync(0xffffffffu, p, gbase + k);
                uint2 raw = hf[s * 32 + lane];
                float2 f01 = __half22float2(*(__half2*)&raw.x);
                float2 f23 = __half22float2(*(__half2*)&raw.y);
                acc.x += pk * f01.x;
                acc.y += pk * f01.y;
                acc.z += pk * f23.x;
                acc.w += pk * f23.y;
            }
        }
    }

    float inv = 1.f / den;
    const float4 bv = ((const float4*)b)[lane];
    float4 o;
    o.x = acc.x * inv + bv.x;
    o.y = acc.y * inv + bv.y;
    o.z = acc.z * inv + bv.z;
    o.w = acc.w * inv + bv.w;
    if (elu) {
        o.x = o.x > 0.f ? o.x : (__expf(o.x) - 1.f);
        o.y = o.y > 0.f ? o.y : (__expf(o.y) - 1.f);
        o.z = o.z > 0.f ? o.z : (__expf(o.z) - 1.f);
        o.w = o.w > 0.f ? o.w : (__expf(o.w) - 1.f);
    }
    ((float4*)out)[d * 32 + lane] = o;
}

// ---------------- host side ----------------
static void run_layer(const float* fin, const float* W, const float* ss,
                      const float* dd, const float* bb, int H, float* outp,
                      int elu, uint2* hf, float* as_, float* ad_,
                      const int* rs, const int* csrc)
{
    gemm_attn<<<(NN + 63) / 64, 256>>>(fin, W, ss, dd, hf, as_, ad_, H);
    gat_gather<<<(NN + 7) / 8, 256>>>(rs, csrc, as_, ad_, hf, bb, outp, H, elu);
}

extern "C" void kernel_launch(void* const* d_in, const int* in_sizes, int n_in,
                              void* d_out, int out_size)
{
    const float* x  = (const float*)d_in[0];
    const int*   ei = (const int*)d_in[1];
    const float* W1 = (const float*)d_in[2];
    const float* s1 = (const float*)d_in[3];
    const float* d1 = (const float*)d_in[4];
    const float* b1 = (const float*)d_in[5];
    const float* W2 = (const float*)d_in[6];
    const float* s2 = (const float*)d_in[7];
    const float* d2 = (const float*)d_in[8];
    const float* b2 = (const float*)d_in[9];
    const float* W3 = (const float*)d_in[10];
    const float* s3 = (const float*)d_in[11];
    const float* d3 = (const float*)d_in[12];
    const float* b3 = (const float*)d_in[13];

    uint2* hf;
    float *f0, *f1, *as_, *ad_;
    int *deg, *rs, *cnt, *csrc;
    cudaGetSymbolAddress((void**)&hf,   g_hf);
    cudaGetSymbolAddress((void**)&f0,   g_f0);
    cudaGetSymbolAddress((void**)&f1,   g_f1);
    cudaGetSymbolAddress((void**)&as_,  g_as);
    cudaGetSymbolAddress((void**)&ad_,  g_ad);
    cudaGetSymbolAddress((void**)&deg,  g_deg);
    cudaGetSymbolAddress((void**)&rs,   g_rs);
    cudaGetSymbolAddress((void**)&cnt,  g_cnt);
    cudaGetSymbolAddress((void**)&csrc, g_src);

    cudaMemsetAsync(deg, 0, NN * sizeof(int));
    cudaMemsetAsync(cnt, 0, NN * sizeof(int));
    const int blk = 256;
    csr_hist<<<(EE + blk - 1) / blk, blk>>>(ei, deg);
    csr_scan<<<1, 1024>>>(deg, rs);
    csr_fill<<<(EE + blk - 1) / blk, blk>>>(ei, rs, cnt, csrc);

    run_layer(x,  W1, s1, d1, b1, 4, f0,            1, hf, as_, ad_, rs, csrc);
    run_layer(f0, W2, s2, d2, b2, 4, f1,            1, hf, as_, ad_, rs, csrc);
    run_layer(f1, W3, s3, d3, b3, 1, (float*)d_out, 0, hf, as_, ad_, rs, csrc);
}

// round 11
// speedup vs baseline: 1.0420x; 1.0420x over previous
#include <cuda_runtime.h>
#include <cuda_fp16.h>

#define NN    100000
#define EDGES 1600000
#define EE    (EDGES + NN)
#define F     128
#define NEG_BIG (-1e30f)

// ---------------- device scratch (no allocation allowed) ----------------
__device__ uint2 g_hf[NN * 32];  // h = X@W in fp16 (128 halves = 32 uint2/node)
__device__ float g_f0[NN * F];
__device__ float g_f1[NN * F];
__device__ float g_as[NN * 4];
__device__ float g_ad[NN * 4];
__device__ float g_mx[NN * 4];   // per (dst,head) softmax max
__device__ float g_dn[NN * 4];   // per (dst,head) softmax denom
__device__ int   g_deg[NN];
__device__ int   g_rs[NN + 1];
__device__ int   g_cnt[NN];
__device__ int   g_src[EE];

// ---------------- CSR build (by destination) ----------------
__global__ void csr_hist(const int* __restrict__ ei, int* __restrict__ deg)
{
    int e = blockIdx.x * blockDim.x + threadIdx.x;
    if (e >= EE) return;
    int d = (e < EDGES) ? ei[EDGES + e] : (e - EDGES);
    atomicAdd(&deg[d], 1);
}

__global__ __launch_bounds__(1024) void csr_scan(const int* __restrict__ deg,
                                                 int* __restrict__ rs)
{
    __shared__ int wsum[32];
    const int t    = threadIdx.x;
    const int lane = t & 31;
    const int w    = t >> 5;
    const int CH   = (NN + 1023) / 1024;
    const int lo   = t * CH;
    const int hi   = min(lo + CH, NN);

    int sum = 0;
    for (int i = lo; i < hi; i++) sum += deg[i];

    int inc = sum;
#pragma unroll
    for (int o = 1; o < 32; o <<= 1) {
        int x = __shfl_up_sync(0xffffffffu, inc, o);
        if (lane >= o) inc += x;
    }
    if (lane == 31) wsum[w] = inc;
    __syncthreads();
    if (w == 0) {
        int v = wsum[lane];
        int s = v;
#pragma unroll
        for (int o = 1; o < 32; o <<= 1) {
            int x = __shfl_up_sync(0xffffffffu, s, o);
            if (lane >= o) s += x;
        }
        wsum[lane] = s - v;
    }
    __syncthreads();

    int run = wsum[w] + inc - sum;
    for (int i = lo; i < hi; i++) { rs[i] = run; run += deg[i]; }
    if (t == 1023) rs[NN] = run;
}

__global__ void csr_fill(const int* __restrict__ ei,
                         const int* __restrict__ rs,
                         int* __restrict__ cnt, int* __restrict__ csrc)
{
    int e = blockIdx.x * blockDim.x + threadIdx.x;
    if (e >= EE) return;
    int s, d;
    if (e < EDGES) { s = ei[e]; d = ei[EDGES + e]; }
    else           { s = d = e - EDGES; }
    int pos = rs[d] + atomicAdd(&cnt[d], 1);
    csrc[pos] = s;
}

// ---------------- scalar register-tiled GEMM + fused attention epilogue ------
// (R7 version: at the fp32 FFMA roofline.) BM=64, BN=128, 256 thr, tile 4x8.
__global__ __launch_bounds__(256) void gemm_attn(
    const float* __restrict__ fin, const float* __restrict__ W,
    const float* __restrict__ att_s, const float* __restrict__ att_d,
    uint2* __restrict__ hf, float* __restrict__ as_, float* __restrict__ ad_,
    int H)
{
    __shared__ float  Xs[64][33];
    __shared__ float4 Ws4[32 * 32];

    const int t    = threadIdx.x;
    const int lane = t & 31;
    const int tcol = t & 15;
    const int trow = t >> 4;
    const int row0 = blockIdx.x * 64;

    float acc[4][8];
#pragma unroll
    for (int i = 0; i < 4; i++)
#pragma unroll
        for (int j = 0; j < 8; j++) acc[i][j] = 0.f;

    for (int kc = 0; kc < 4; kc++) {
#pragma unroll
        for (int i = 0; i < 2; i++) {
            int idx = t + 256 * i;
            int r = idx >> 3, c = idx & 7;
            int gr = min(row0 + r, NN - 1);
            float4 v = *(const float4*)&fin[gr * F + kc * 32 + 4 * c];
            Xs[r][4 * c + 0] = v.x;
            Xs[r][4 * c + 1] = v.y;
            Xs[r][4 * c + 2] = v.z;
            Xs[r][4 * c + 3] = v.w;
        }
#pragma unroll
        for (int i = 0; i < 4; i++) {
            int idx = t + 256 * i;
            int k = idx >> 5, c = idx & 31;
            Ws4[k * 32 + c] = *(const float4*)&W[(kc * 32 + k) * F + 4 * c];
        }
        __syncthreads();

#pragma unroll
        for (int k = 0; k < 32; k++) {
            float a0 = Xs[trow * 4 + 0][k];
            float a1 = Xs[trow * 4 + 1][k];
            float a2 = Xs[trow * 4 + 2][k];
            float a3 = Xs[trow * 4 + 3][k];
            float4 b0 = Ws4[k * 32 + tcol];
            float4 b1 = Ws4[k * 32 + 16 + tcol];
            acc[0][0] += a0 * b0.x; acc[0][1] += a0 * b0.y;
            acc[0][2] += a0 * b0.z; acc[0][3] += a0 * b0.w;
            acc[0][4] += a0 * b1.x; acc[0][5] += a0 * b1.y;
            acc[0][6] += a0 * b1.z; acc[0][7] += a0 * b1.w;
            acc[1][0] += a1 * b0.x; acc[1][1] += a1 * b0.y;
            acc[1][2] += a1 * b0.z; acc[1][3] += a1 * b0.w;
            acc[1][4] += a1 * b1.x; acc[1][5] += a1 * b1.y;
            acc[1][6] += a1 * b1.z; acc[1][7] += a1 * b1.w;
            acc[2][0] += a2 * b0.x; acc[2][1] += a2 * b0.y;
            acc[2][2] += a2 * b0.z; acc[2][3] += a2 * b0.w;
            acc[2][4] += a2 * b1.x; acc[2][5] += a2 * b1.y;
            acc[2][6] += a2 * b1.z; acc[2][7] += a2 * b1.w;
            acc[3][0] += a3 * b0.x; acc[3][1] += a3 * b0.y;
            acc[3][2] += a3 * b0.z; acc[3][3] += a3 * b0.w;
            acc[3][4] += a3 * b1.x; acc[3][5] += a3 * b1.y;
            acc[3][6] += a3 * b1.z; acc[3][7] += a3 * b1.w;
        }
        __syncthreads();
    }

    const float4 sA = ((const float4*)att_s)[tcol];
    const float4 sB = ((const float4*)att_s)[16 + tcol];
    const float4 dA = ((const float4*)att_d)[tcol];
    const float4 dB = ((const float4*)att_d)[16 + tcol];

#pragma unroll
    for (int i = 0; i < 4; i++) {
        int gr = row0 + trow * 4 + i;
        bool ok = gr < NN;
        if (ok) {
            __half2 p0 = __floats2half2_rn(acc[i][0], acc[i][1]);
            __half2 p1 = __floats2half2_rn(acc[i][2], acc[i][3]);
            __half2 p2 = __floats2half2_rn(acc[i][4], acc[i][5]);
            __half2 p3 = __floats2half2_rn(acc[i][6], acc[i][7]);
            hf[gr * 32 + tcol]      = make_uint2(*(unsigned*)&p0, *(unsigned*)&p1);
            hf[gr * 32 + 16 + tcol] = make_uint2(*(unsigned*)&p2, *(unsigned*)&p3);
        }
        float psA = acc[i][0] * sA.x + acc[i][1] * sA.y + acc[i][2] * sA.z + acc[i][3] * sA.w;
        float psB = acc[i][4] * sB.x + acc[i][5] * sB.y + acc[i][6] * sB.z + acc[i][7] * sB.w;
        float pdA = acc[i][0] * dA.x + acc[i][1] * dA.y + acc[i][2] * dA.z + acc[i][3] * dA.w;
        float pdB = acc[i][4] * dB.x + acc[i][5] * dB.y + acc[i][6] * dB.z + acc[i][7] * dB.w;
        if (H == 4) {
#pragma unroll
            for (int o = 1; o < 8; o <<= 1) {
                psA += __shfl_xor_sync(0xffffffffu, psA, o);
                psB += __shfl_xor_sync(0xffffffffu, psB, o);
                pdA += __shfl_xor_sync(0xffffffffu, pdA, o);
                pdB += __shfl_xor_sync(0xffffffffu, pdB, o);
            }
            if ((lane & 7) == 0 && ok) {
                int h0 = (lane >> 3) & 1;
                as_[gr * 4 + h0]     = psA;
                as_[gr * 4 + h0 + 2] = psB;
                ad_[gr * 4 + h0]     = pdA;
                ad_[gr * 4 + h0 + 2] = pdB;
            }
        } else {
            float s = psA + psB, dd = pdA + pdB;
#pragma unroll
            for (int o = 1; o < 16; o <<= 1) {
                s  += __shfl_xor_sync(0xffffffffu, s,  o);
                dd += __shfl_xor_sync(0xffffffffu, dd, o);
            }
            if ((lane & 15) == 0 && ok) { as_[gr] = s; ad_[gr] = dd; }
        }
    }
}

// ---------------- pass 1: exact per-(dst,head) softmax max + denominator -----
__device__ __forceinline__ void online(float& m, float& den, float v) {
    float mn = fmaxf(m, v);
    den = den * __expf(m - mn) + __expf(v - mn);
    m = mn;
}
__device__ __forceinline__ void combine(float& m, float& den, float om, float od) {
    float mn = fmaxf(m, om);
    den = den * __expf(m - mn) + od * __expf(om - mn);
    m = mn;
}

__global__ __launch_bounds__(256) void gat_maxden(
    const int* __restrict__ rs, const int* __restrict__ csrc,
    const float* __restrict__ as_, const float* __restrict__ ad_,
    float* __restrict__ mx, float* __restrict__ dn, int H)
{
    const int warp = (blockIdx.x * blockDim.x + threadIdx.x) >> 5;
    const int lane = threadIdx.x & 31;
    if (warp >= NN) return;
    const int d = warp;
    const int start = rs[d], end = rs[d + 1];

    if (H == 4) {
        const float4 adv = ((const float4*)ad_)[d];
        float4 m = make_float4(NEG_BIG, NEG_BIG, NEG_BIG, NEG_BIG);
        float4 den = make_float4(0.f, 0.f, 0.f, 0.f);
        for (int j = start + lane; j < end; j += 32) {
            int s = csrc[j];
            float4 a = ((const float4*)as_)[s];
            float vx = a.x + adv.x; vx = vx > 0.f ? vx : 0.2f * vx;
            float vy = a.y + adv.y; vy = vy > 0.f ? vy : 0.2f * vy;
            float vz = a.z + adv.z; vz = vz > 0.f ? vz : 0.2f * vz;
            float vw = a.w + adv.w; vw = vw > 0.f ? vw : 0.2f * vw;
            online(m.x, den.x, vx);
            online(m.y, den.y, vy);
            online(m.z, den.z, vz);
            online(m.w, den.w, vw);
        }
#pragma unroll
        for (int o = 16; o > 0; o >>= 1) {
            float omx = __shfl_xor_sync(0xffffffffu, m.x, o);
            float odx = __shfl_xor_sync(0xffffffffu, den.x, o);
            float omy = __shfl_xor_sync(0xffffffffu, m.y, o);
            float ody = __shfl_xor_sync(0xffffffffu, den.y, o);
            float omz = __shfl_xor_sync(0xffffffffu, m.z, o);
            float odz = __shfl_xor_sync(0xffffffffu, den.z, o);
            float omw = __shfl_xor_sync(0xffffffffu, m.w, o);
            float odw = __shfl_xor_sync(0xffffffffu, den.w, o);
            combine(m.x, den.x, omx, odx);
            combine(m.y, den.y, omy, ody);
            combine(m.z, den.z, omz, odz);
            combine(m.w, den.w, omw, odw);
        }
        if (lane == 0) {
            ((float4*)mx)[d] = m;
            ((float4*)dn)[d] = den;
        }
    } else {
        const float adv = ad_[d];
        float m = NEG_BIG, den = 0.f;
        for (int j = start + lane; j < end; j += 32) {
            int s = csrc[j];
            float v = as_[s] + adv;
            v = v > 0.f ? v : 0.2f * v;
            online(m, den, v);
        }
#pragma unroll
        for (int o = 16; o > 0; o >>= 1) {
            float om = __shfl_xor_sync(0xffffffffu, m, o);
            float od = __shfl_xor_sync(0xffffffffu, den, o);
            combine(m, den, om, od);
        }
        if (lane == 0) { mx[d * 4] = m; dn[d * 4] = den; }
    }
}

// ---------------- pass 2: aggregate with precomputed alpha -------------------
// No reductions, no online rescale: blocks are independent, full latency overlap.
__global__ __launch_bounds__(256) void gat_gather(
    const int* __restrict__ rs, const int* __restrict__ csrc,
    const float* __restrict__ as_, const float* __restrict__ ad_,
    const float* __restrict__ mx, const float* __restrict__ dn,
    const uint2* __restrict__ hf, const float* __restrict__ b,
    float* __restrict__ out, int H, int elu)
{
    const int warp = (blockIdx.x * blockDim.x + threadIdx.x) >> 5;
    const int lane = threadIdx.x & 31;
    if (warp >= NN) return;
    const int d = warp;

    const int h = (H == 4) ? (lane >> 3) : 0;
    const float adv = ad_[d * H + h];
    const float mh  = mx[d * 4 + h];
    const float inv = 1.f / dn[d * 4 + h];

    float4 acc = make_float4(0.f, 0.f, 0.f, 0.f);

    const int start = rs[d], end = rs[d + 1];
    const int gbase = lane & 24;

    for (int j = start; j < end; j += 32) {
        int sj = (j + lane < end) ? csrc[j + lane] : 0;
        int nb = min(32, end - j);
        for (int base = 0; base < nb; base += 8) {
            int nk = min(8, nb - base);
            int s_my = __shfl_sync(0xffffffffu, sj, base + (lane & 7));
            float alpha = 0.f;
            if ((lane & 7) < nk) {
                float vv = as_[s_my * H + h] + adv;
                vv = vv > 0.f ? vv : 0.2f * vv;
                alpha = __expf(vv - mh) * inv;
            }
            for (int k = 0; k < nk; k++) {
                int   s  = __shfl_sync(0xffffffffu, sj, base + k);
                float pk = __shfl_sync(0xffffffffu, alpha, gbase + k);
                uint2 raw = hf[s * 32 + lane];
                float2 f01 = __half22float2(*(__half2*)&raw.x);
                float2 f23 = __half22float2(*(__half2*)&raw.y);
                acc.x += pk * f01.x;
                acc.y += pk * f01.y;
                acc.z += pk * f23.x;
                acc.w += pk * f23.y;
            }
        }
    }

    const float4 bv = ((const float4*)b)[lane];
    float4 o;
    o.x = acc.x + bv.x;
    o.y = acc.y + bv.y;
    o.z = acc.z + bv.z;
    o.w = acc.w + bv.w;
    if (elu) {
        o.x = o.x > 0.f ? o.x : (__expf(o.x) - 1.f);
        o.y = o.y > 0.f ? o.y : (__expf(o.y) - 1.f);
        o.z = o.z > 0.f ? o.z : (__expf(o.z) - 1.f);
        o.w = o.w > 0.f ? o.w : (__expf(o.w) - 1.f);
    }
    ((float4*)out)[d * 32 + lane] = o;
}

// ---------------- host side ----------------
static void run_layer(const float* fin, const float* W, const float* ss,
                      const float* dd, const float* bb, int H, float* outp,
                      int elu, uint2* hf, float* as_, float* ad_,
                      float* mx, float* dn, const int* rs, const int* csrc)
{
    gemm_attn<<<(NN + 63) / 64, 256>>>(fin, W, ss, dd, hf, as_, ad_, H);
    gat_maxden<<<(NN + 7) / 8, 256>>>(rs, csrc, as_, ad_, mx, dn, H);
    gat_gather<<<(NN + 7) / 8, 256>>>(rs, csrc, as_, ad_, mx, dn, hf, bb,
                                      outp, H, elu);
}

extern "C" void kernel_launch(void* const* d_in, const int* in_sizes, int n_in,
                              void* d_out, int out_size)
{
    const float* x  = (const float*)d_in[0];
    const int*   ei = (const int*)d_in[1];
    const float* W1 = (const float*)d_in[2];
    const float* s1 = (const float*)d_in[3];
    const float* d1 = (const float*)d_in[4];
    const float* b1 = (const float*)d_in[5];
    const float* W2 = (const float*)d_in[6];
    const float* s2 = (const float*)d_in[7];
    const float* d2 = (const float*)d_in[8];
    const float* b2 = (const float*)d_in[9];
    const float* W3 = (const float*)d_in[10];
    const float* s3 = (const float*)d_in[11];
    const float* d3 = (const float*)d_in[12];
    const float* b3 = (const float*)d_in[13];

    uint2* hf;
    float *f0, *f1, *as_, *ad_, *mx, *dn;
    int *deg, *rs, *cnt, *csrc;
    cudaGetSymbolAddress((void**)&hf,   g_hf);
    cudaGetSymbolAddress((void**)&f0,   g_f0);
    cudaGetSymbolAddress((void**)&f1,   g_f1);
    cudaGetSymbolAddress((void**)&as_,  g_as);
    cudaGetSymbolAddress((void**)&ad_,  g_ad);
    cudaGetSymbolAddress((void**)&mx,   g_mx);
    cudaGetSymbolAddress((void**)&dn,   g_dn);
    cudaGetSymbolAddress((void**)&deg,  g_deg);
    cudaGetSymbolAddress((void**)&rs,   g_rs);
    cudaGetSymbolAddress((void**)&cnt,  g_cnt);
    cudaGetSymbolAddress((void**)&csrc, g_src);

    cudaMemsetAsync(deg, 0, NN * sizeof(int));
    cudaMemsetAsync(cnt, 0, NN * sizeof(int));
    const int blk = 256;
    csr_hist<<<(EE + blk - 1) / blk, blk>>>(ei, deg);
    csr_scan<<<1, 1024>>>(deg, rs);
    csr_fill<<<(EE + blk - 1) / blk, blk>>>(ei, rs, cnt, csrc);

    run_layer(x,  W1, s1, d1, b1, 4, f0,            1, hf, as_, ad_, mx, dn, rs, csrc);
    run_layer(f0, W2, s2, d2, b2, 4, f1,            1, hf, as_, ad_, mx, dn, rs, csrc);
    run_layer(f1, W3, s3, d3, b3, 1, (float*)d_out, 0, hf, as_, ad_, mx, dn, rs, csrc);
}

// round 14
// speedup vs baseline: 1.1041x; 1.0595x over previous
#include <cuda_runtime.h>
#include <cuda_fp16.h>

#define NN    100000
#define EDGES 1600000
#define EE    (EDGES + NN)
#define F     128
#define NEG_BIG (-1e30f)

// ---------------- device scratch (no allocation allowed) ----------------
__device__ uint2  g_hf[NN * 32];   // h = X@W in fp16 (128 halves/node)
__device__ float  g_f0[NN * F];
__device__ float  g_f1[NN * F];
__device__ float  g_as[NN * 4];
__device__ float  g_ad[NN * 4];
__device__ float4 g_alpha[EE];     // per-edge softmax weights (4 heads) / float for H=1
__device__ int    g_deg[NN];
__device__ int    g_rs[NN + 1];
__device__ int    g_cnt[NN];
__device__ int    g_src[EE];

// ---------------- CSR build (by destination) ----------------
__global__ void csr_hist(const int* __restrict__ ei, int* __restrict__ deg)
{
    int e = blockIdx.x * blockDim.x + threadIdx.x;
    if (e >= EE) return;
    int d = (e < EDGES) ? ei[EDGES + e] : (e - EDGES);
    atomicAdd(&deg[d], 1);
}

__global__ __launch_bounds__(1024) void csr_scan(const int* __restrict__ deg,
                                                 int* __restrict__ rs)
{
    __shared__ int wsum[32];
    const int t    = threadIdx.x;
    const int lane = t & 31;
    const int w    = t >> 5;
    const int CH   = (NN + 1023) / 1024;
    const int lo   = t * CH;
    const int hi   = min(lo + CH, NN);

    int sum = 0;
    for (int i = lo; i < hi; i++) sum += deg[i];

    int inc = sum;
#pragma unroll
    for (int o = 1; o < 32; o <<= 1) {
        int x = __shfl_up_sync(0xffffffffu, inc, o);
        if (lane >= o) inc += x;
    }
    if (lane == 31) wsum[w] = inc;
    __syncthreads();
    if (w == 0) {
        int v = wsum[lane];
        int s = v;
#pragma unroll
        for (int o = 1; o < 32; o <<= 1) {
            int x = __shfl_up_sync(0xffffffffu, s, o);
            if (lane >= o) s += x;
        }
        wsum[lane] = s - v;
    }
    __syncthreads();

    int run = wsum[w] + inc - sum;
    for (int i = lo; i < hi; i++) { rs[i] = run; run += deg[i]; }
    if (t == 1023) rs[NN] = run;
}

__global__ void csr_fill(const int* __restrict__ ei,
                         const int* __restrict__ rs,
                         int* __restrict__ cnt, int* __restrict__ csrc)
{
    int e = blockIdx.x * blockDim.x + threadIdx.x;
    if (e >= EE) return;
    int s, d;
    if (e < EDGES) { s = ei[e]; d = ei[EDGES + e]; }
    else           { s = d = e - EDGES; }
    int pos = rs[d] + atomicAdd(&cnt[d], 1);
    csrc[pos] = s;
}

// ---------------- scalar register-tiled GEMM + fused attention epilogue ------
// (R7 version: at the fp32 FFMA roofline.) BM=64, BN=128, 256 thr, tile 4x8.
__global__ __launch_bounds__(256) void gemm_attn(
    const float* __restrict__ fin, const float* __restrict__ W,
    const float* __restrict__ att_s, const float* __restrict__ att_d,
    uint2* __restrict__ hf, float* __restrict__ as_, float* __restrict__ ad_,
    int H)
{
    __shared__ float  Xs[64][33];
    __shared__ float4 Ws4[32 * 32];

    const int t    = threadIdx.x;
    const int lane = t & 31;
    const int tcol = t & 15;
    const int trow = t >> 4;
    const int row0 = blockIdx.x * 64;

    float acc[4][8];
#pragma unroll
    for (int i = 0; i < 4; i++)
#pragma unroll
        for (int j = 0; j < 8; j++) acc[i][j] = 0.f;

    for (int kc = 0; kc < 4; kc++) {
#pragma unroll
        for (int i = 0; i < 2; i++) {
            int idx = t + 256 * i;
            int r = idx >> 3, c = idx & 7;
            int gr = min(row0 + r, NN - 1);
            float4 v = *(const float4*)&fin[gr * F + kc * 32 + 4 * c];
            Xs[r][4 * c + 0] = v.x;
            Xs[r][4 * c + 1] = v.y;
            Xs[r][4 * c + 2] = v.z;
            Xs[r][4 * c + 3] = v.w;
        }
#pragma unroll
        for (int i = 0; i < 4; i++) {
            int idx = t + 256 * i;
            int k = idx >> 5, c = idx & 31;
            Ws4[k * 32 + c] = *(const float4*)&W[(kc * 32 + k) * F + 4 * c];
        }
        __syncthreads();

#pragma unroll
        for (int k = 0; k < 32; k++) {
            float a0 = Xs[trow * 4 + 0][k];
            float a1 = Xs[trow * 4 + 1][k];
            float a2 = Xs[trow * 4 + 2][k];
            float a3 = Xs[trow * 4 + 3][k];
            float4 b0 = Ws4[k * 32 + tcol];
            float4 b1 = Ws4[k * 32 + 16 + tcol];
            acc[0][0] += a0 * b0.x; acc[0][1] += a0 * b0.y;
            acc[0][2] += a0 * b0.z; acc[0][3] += a0 * b0.w;
            acc[0][4] += a0 * b1.x; acc[0][5] += a0 * b1.y;
            acc[0][6] += a0 * b1.z; acc[0][7] += a0 * b1.w;
            acc[1][0] += a1 * b0.x; acc[1][1] += a1 * b0.y;
            acc[1][2] += a1 * b0.z; acc[1][3] += a1 * b0.w;
            acc[1][4] += a1 * b1.x; acc[1][5] += a1 * b1.y;
            acc[1][6] += a1 * b1.z; acc[1][7] += a1 * b1.w;
            acc[2][0] += a2 * b0.x; acc[2][1] += a2 * b0.y;
            acc[2][2] += a2 * b0.z; acc[2][3] += a2 * b0.w;
            acc[2][4] += a2 * b1.x; acc[2][5] += a2 * b1.y;
            acc[2][6] += a2 * b1.z; acc[2][7] += a2 * b1.w;
            acc[3][0] += a3 * b0.x; acc[3][1] += a3 * b0.y;
            acc[3][2] += a3 * b0.z; acc[3][3] += a3 * b0.w;
            acc[3][4] += a3 * b1.x; acc[3][5] += a3 * b1.y;
            acc[3][6] += a3 * b1.z; acc[3][7] += a3 * b1.w;
        }
        __syncthreads();
    }

    const float4 sA = ((const float4*)att_s)[tcol];
    const float4 sB = ((const float4*)att_s)[16 + tcol];
    const float4 dA = ((const float4*)att_d)[tcol];
    const float4 dB = ((const float4*)att_d)[16 + tcol];

#pragma unroll
    for (int i = 0; i < 4; i++) {
        int gr = row0 + trow * 4 + i;
        bool ok = gr < NN;
        if (ok) {
            __half2 p0 = __floats2half2_rn(acc[i][0], acc[i][1]);
            __half2 p1 = __floats2half2_rn(acc[i][2], acc[i][3]);
            __half2 p2 = __floats2half2_rn(acc[i][4], acc[i][5]);
            __half2 p3 = __floats2half2_rn(acc[i][6], acc[i][7]);
            hf[gr * 32 + tcol]      = make_uint2(*(unsigned*)&p0, *(unsigned*)&p1);
            hf[gr * 32 + 16 + tcol] = make_uint2(*(unsigned*)&p2, *(unsigned*)&p3);
        }
        float psA = acc[i][0] * sA.x + acc[i][1] * sA.y + acc[i][2] * sA.z + acc[i][3] * sA.w;
        float psB = acc[i][4] * sB.x + acc[i][5] * sB.y + acc[i][6] * sB.z + acc[i][7] * sB.w;
        float pdA = acc[i][0] * dA.x + acc[i][1] * dA.y + acc[i][2] * dA.z + acc[i][3] * dA.w;
        float pdB = acc[i][4] * dB.x + acc[i][5] * dB.y + acc[i][6] * dB.z + acc[i][7] * dB.w;
        if (H == 4) {
#pragma unroll
            for (int o = 1; o < 8; o <<= 1) {
                psA += __shfl_xor_sync(0xffffffffu, psA, o);
                psB += __shfl_xor_sync(0xffffffffu, psB, o);
                pdA += __shfl_xor_sync(0xffffffffu, pdA, o);
                pdB += __shfl_xor_sync(0xffffffffu, pdB, o);
            }
            if ((lane & 7) == 0 && ok) {
                int h0 = (lane >> 3) & 1;
                as_[gr * 4 + h0]     = psA;
                as_[gr * 4 + h0 + 2] = psB;
                ad_[gr * 4 + h0]     = pdA;
                ad_[gr * 4 + h0 + 2] = pdB;
            }
        } else {
            float s = psA + psB, dd = pdA + pdB;
#pragma unroll
            for (int o = 1; o < 16; o <<= 1) {
                s  += __shfl_xor_sync(0xffffffffu, s,  o);
                dd += __shfl_xor_sync(0xffffffffu, dd, o);
            }
            if ((lane & 15) == 0 && ok) { as_[gr] = s; ad_[gr] = dd; }
        }
    }
}

// ---------------- pass 1: exact softmax stats, then per-edge alpha -----------
__device__ __forceinline__ void online(float& m, float& den, float v) {
    float mn = fmaxf(m, v);
    den = den * __expf(m - mn) + __expf(v - mn);
    m = mn;
}
__device__ __forceinline__ void combine(float& m, float& den, float om, float od) {
    float mn = fmaxf(m, om);
    den = den * __expf(m - mn) + od * __expf(om - mn);
    m = mn;
}

__global__ __launch_bounds__(256) void gat_alpha(
    const int* __restrict__ rs, const int* __restrict__ csrc,
    const float* __restrict__ as_, const float* __restrict__ ad_,
    float4* __restrict__ alpha, int H)
{
    const int warp = (blockIdx.x * blockDim.x + threadIdx.x) >> 5;
    const int lane = threadIdx.x & 31;
    if (warp >= NN) return;
    const int d = warp;
    const int start = rs[d], end = rs[d + 1];

    if (H == 4) {
        const float4 adv = ((const float4*)ad_)[d];
        float4 m = make_float4(NEG_BIG, NEG_BIG, NEG_BIG, NEG_BIG);
        float4 den = make_float4(0.f, 0.f, 0.f, 0.f);
        for (int j = start + lane; j < end; j += 32) {
            int s = csrc[j];
            float4 a = ((const float4*)as_)[s];
            float vx = a.x + adv.x; vx = vx > 0.f ? vx : 0.2f * vx;
            float vy = a.y + adv.y; vy = vy > 0.f ? vy : 0.2f * vy;
            float vz = a.z + adv.z; vz = vz > 0.f ? vz : 0.2f * vz;
            float vw = a.w + adv.w; vw = vw > 0.f ? vw : 0.2f * vw;
            online(m.x, den.x, vx);
            online(m.y, den.y, vy);
            online(m.z, den.z, vz);
            online(m.w, den.w, vw);
        }
#pragma unroll
        for (int o = 16; o > 0; o >>= 1) {
            float om, od;
            om = __shfl_xor_sync(0xffffffffu, m.x, o);
            od = __shfl_xor_sync(0xffffffffu, den.x, o);
            combine(m.x, den.x, om, od);
            om = __shfl_xor_sync(0xffffffffu, m.y, o);
            od = __shfl_xor_sync(0xffffffffu, den.y, o);
            combine(m.y, den.y, om, od);
            om = __shfl_xor_sync(0xffffffffu, m.z, o);
            od = __shfl_xor_sync(0xffffffffu, den.z, o);
            combine(m.z, den.z, om, od);
            om = __shfl_xor_sync(0xffffffffu, m.w, o);
            od = __shfl_xor_sync(0xffffffffu, den.w, o);
            combine(m.w, den.w, om, od);
        }
        float4 inv = make_float4(1.f / den.x, 1.f / den.y,
                                 1.f / den.z, 1.f / den.w);
        for (int j = start + lane; j < end; j += 32) {
            int s = csrc[j];
            float4 a = ((const float4*)as_)[s];
            float vx = a.x + adv.x; vx = vx > 0.f ? vx : 0.2f * vx;
            float vy = a.y + adv.y; vy = vy > 0.f ? vy : 0.2f * vy;
            float vz = a.z + adv.z; vz = vz > 0.f ? vz : 0.2f * vz;
            float vw = a.w + adv.w; vw = vw > 0.f ? vw : 0.2f * vw;
            float4 al;
            al.x = __expf(vx - m.x) * inv.x;
            al.y = __expf(vy - m.y) * inv.y;
            al.z = __expf(vz - m.z) * inv.z;
            al.w = __expf(vw - m.w) * inv.w;
            alpha[j] = al;
        }
    } else {
        const float adv = ad_[d];
        float m = NEG_BIG, den = 0.f;
        for (int j = start + lane; j < end; j += 32) {
            int s = csrc[j];
            float v = as_[s] + adv;
            v = v > 0.f ? v : 0.2f * v;
            online(m, den, v);
        }
#pragma unroll
        for (int o = 16; o > 0; o >>= 1) {
            float om = __shfl_xor_sync(0xffffffffu, m, o);
            float od = __shfl_xor_sync(0xffffffffu, den, o);
            combine(m, den, om, od);
        }
        float inv = 1.f / den;
        float* a1 = (float*)alpha;
        for (int j = start + lane; j < end; j += 32) {
            int s = csrc[j];
            float v = as_[s] + adv;
            v = v > 0.f ? v : 0.2f * v;
            a1[j] = __expf(v - m) * inv;
        }
    }
}

// ---------------- pass 2: shuffle-free pair-edge gather ----------------------
// 16 lanes per edge (uint4 = 8 channels/lane); each warp runs 2 edges at once.
// Inner loop: 1 shfl(s) + 1 alpha load (j-indexed, early-issue) + 1 LDG.128
// + 8 FFMA. No reductions, no cross-iteration deps except the accumulators.
__global__ __launch_bounds__(256) void gat_gather(
    const int* __restrict__ rs, const int* __restrict__ csrc,
    const float4* __restrict__ alpha, const uint4* __restrict__ hfu,
    const float* __restrict__ b, float* __restrict__ out, int H, int elu)
{
    const int warp = (blockIdx.x * blockDim.x + threadIdx.x) >> 5;
    const int lane = threadIdx.x & 31;
    if (warp >= NN) return;
    const int d    = warp;
    const int li   = lane & 15;
    const int half = lane >> 4;
    const int head = (H == 4) ? (li >> 2) : 0;

    float acc[8];
#pragma unroll
    for (int i = 0; i < 8; i++) acc[i] = 0.f;

    const int start = rs[d], end = rs[d + 1];
    const float* a1 = (const float*)alpha;

    for (int j0 = start; j0 < end; j0 += 32) {
        int sj = (j0 + lane < end) ? csrc[j0 + lane] : 0;
        int nb = min(32, end - j0);
        for (int p = 0; p < nb; p += 2) {
            int  idx = p + half;
            int  s   = __shfl_sync(0xffffffffu, sj, idx);
            bool val = idx < nb;
            float al = 0.f;
            if (val) {
                al = (H == 4) ? ((const float*)(alpha + (j0 + idx)))[head]
                              : a1[j0 + idx];
            }
            uint4 raw = hfu[s * 16 + li];
            float2 f0 = __half22float2(*(__half2*)&raw.x);
            float2 f1 = __half22float2(*(__half2*)&raw.y);
            float2 f2 = __half22float2(*(__half2*)&raw.z);
            float2 f3 = __half22float2(*(__half2*)&raw.w);
            acc[0] += al * f0.x; acc[1] += al * f0.y;
            acc[2] += al * f1.x; acc[3] += al * f1.y;
            acc[4] += al * f2.x; acc[5] += al * f2.y;
            acc[6] += al * f3.x; acc[7] += al * f3.y;
        }
    }

    // combine the two half-warp edge subsets
#pragma unroll
    for (int i = 0; i < 8; i++)
        acc[i] += __shfl_xor_sync(0xffffffffu, acc[i], 16);

    if (half == 0) {
        float4 b0 = ((const float4*)b)[li * 2];
        float4 b1 = ((const float4*)b)[li * 2 + 1];
        float o0x = acc[0] + b0.x, o0y = acc[1] + b0.y;
        float o0z = acc[2] + b0.z, o0w = acc[3] + b0.w;
        float o1x = acc[4] + b1.x, o1y = acc[5] + b1.y;
        float o1z = acc[6] + b1.z, o1w = acc[7] + b1.w;
        if (elu) {
            o0x = o0x > 0.f ? o0x : (__expf(o0x) - 1.f);
            o0y = o0y > 0.f ? o0y : (__expf(o0y) - 1.f);
            o0z = o0z > 0.f ? o0z : (__expf(o0z) - 1.f);
            o0w = o0w > 0.f ? o0w : (__expf(o0w) - 1.f);
            o1x = o1x > 0.f ? o1x : (__expf(o1x) - 1.f);
            o1y = o1y > 0.f ? o1y : (__expf(o1y) - 1.f);
            o1z = o1z > 0.f ? o1z : (__expf(o1z) - 1.f);
            o1w = o1w > 0.f ? o1w : (__expf(o1w) - 1.f);
        }
        ((float4*)out)[d * 32 + li * 2]     = make_float4(o0x, o0y, o0z, o0w);
        ((float4*)out)[d * 32 + li * 2 + 1] = make_float4(o1x, o1y, o1z, o1w);
    }
}

// ---------------- host side ----------------
static void run_layer(const float* fin, const float* W, const float* ss,
                      const float* dd, const float* bb, int H, float* outp,
                      int elu, uint2* hf, float* as_, float* ad_,
                      float4* alpha, const int* rs, const int* csrc)
{
    gemm_attn<<<(NN + 63) / 64, 256>>>(fin, W, ss, dd, hf, as_, ad_, H);
    gat_alpha<<<(NN + 7) / 8, 256>>>(rs, csrc, as_, ad_, alpha, H);
    gat_gather<<<(NN + 7) / 8, 256>>>(rs, csrc, alpha, (const uint4*)hf,
                                      bb, outp, H, elu);
}

extern "C" void kernel_launch(void* const* d_in, const int* in_sizes, int n_in,
                              void* d_out, int out_size)
{
    const float* x  = (const float*)d_in[0];
    const int*   ei = (const int*)d_in[1];
    const float* W1 = (const float*)d_in[2];
    const float* s1 = (const float*)d_in[3];
    const float* d1 = (const float*)d_in[4];
    const float* b1 = (const float*)d_in[5];
    const float* W2 = (const float*)d_in[6];
    const float* s2 = (const float*)d_in[7];
    const float* d2 = (const float*)d_in[8];
    const float* b2 = (const float*)d_in[9];
    const float* W3 = (const float*)d_in[10];
    const float* s3 = (const float*)d_in[11];
    const float* d3 = (const float*)d_in[12];
    const float* b3 = (const float*)d_in[13];

    uint2* hf;
    float *f0, *f1, *as_, *ad_;
    float4* alpha;
    int *deg, *rs, *cnt, *csrc;
    cudaGetSymbolAddress((void**)&hf,    g_hf);
    cudaGetSymbolAddress((void**)&f0,    g_f0);
    cudaGetSymbolAddress((void**)&f1,    g_f1);
    cudaGetSymbolAddress((void**)&as_,   g_as);
    cudaGetSymbolAddress((void**)&ad_,   g_ad);
    cudaGetSymbolAddress((void**)&alpha, g_alpha);
    cudaGetSymbolAddress((void**)&deg,   g_deg);
    cudaGetSymbolAddress((void**)&rs,    g_rs);
    cudaGetSymbolAddress((void**)&cnt,   g_cnt);
    cudaGetSymbolAddress((void**)&csrc,  g_src);

    cudaMemsetAsync(deg, 0, NN * sizeof(int));
    cudaMemsetAsync(cnt, 0, NN * sizeof(int));
    const int blk = 256;
    csr_hist<<<(EE + blk - 1) / blk, blk>>>(ei, deg);
    csr_scan<<<1, 1024>>>(deg, rs);
    csr_fill<<<(EE + blk - 1) / blk, blk>>>(ei, rs, cnt, csrc);

    run_layer(x,  W1, s1, d1, b1, 4, f0,            1, hf, as_, ad_, alpha, rs, csrc);
    run_layer(f0, W2, s2, d2, b2, 4, f1,            1, hf, as_, ad_, alpha, rs, csrc);
    run_layer(f1, W3, s3, d3, b3, 1, (float*)d_out, 0, hf, as_, ad_, alpha, rs, csrc);
}